// round 2
// baseline (speedup 1.0000x reference)
#include <cuda_runtime.h>
#include <cuda_bf16.h>

// Problem constants
#define INPUT_DIM 4
#define H1 64          // hidden_dim
#define H2 32          // latent_dim
#define BATCH 64
#define SEQ 4096

#define G1 (4*H1)      // 256 layer-1 gate lanes
#define G2 (4*H2)      // 128 layer-2 gate lanes
#define NTHREADS (G1 + G2)  // 384

// ---- packed f32x2 helpers (sm_103a FFMA2) ----
__device__ __forceinline__ unsigned long long pk2(float a, float b) {
    unsigned long long r;
    asm("mov.b64 %0, {%1, %2};" : "=l"(r) : "f"(a), "f"(b));
    return r;
}
__device__ __forceinline__ void upk2(unsigned long long v, float& a, float& b) {
    asm("mov.b64 {%0, %1}, %2;" : "=f"(a), "=f"(b) : "l"(v));
}
__device__ __forceinline__ unsigned long long fma2(unsigned long long a,
                                                   unsigned long long b,
                                                   unsigned long long c) {
    unsigned long long d;
    asm("fma.rn.f32x2 %0, %1, %2, %3;" : "=l"(d) : "l"(a), "l"(b), "l"(c));
    return d;
}
__device__ __forceinline__ unsigned long long add2(unsigned long long a,
                                                   unsigned long long b) {
    unsigned long long d;
    asm("add.rn.f32x2 %0, %1, %2;" : "=l"(d) : "l"(a), "l"(b));
    return d;
}

__device__ __forceinline__ float tanh_f(float x) {
    // tanh(x) = 2*sigmoid(2x) - 1
    const float e = __expf(-2.0f * x);
    return __fmaf_rn(2.0f, __fdividef(1.0f, 1.0f + e), -1.0f);
}

__global__ void __launch_bounds__(NTHREADS, 1)
lstm2_kernel(const float* __restrict__ x,
             const float* __restrict__ W_ih1, const float* __restrict__ W_hh1,
             const float* __restrict__ b_ih1, const float* __restrict__ b_hh1,
             const float* __restrict__ W_ih2, const float* __restrict__ W_hh2,
             const float* __restrict__ b_ih2, const float* __restrict__ b_hh2,
             float* __restrict__ out)
{
    const int b   = blockIdx.x;
    const int tid = threadIdx.x;

    // double-buffered hidden states; one __syncthreads per step suffices
    __shared__ __align__(16) float h1_sh[2][H1];
    __shared__ __align__(16) float h2_sh[2][H2];

    // Lane layout: 4 lanes per hidden unit, one gate per lane.
    // tid < 256 : layer-1, unit u = p>>2, gate q = p&3 (i,f,g,o), row g = q*H1+u
    // tid >= 256: layer-2, unit u = p>>2, gate q = p&3,           row g = q*H2+u
    const bool isL1 = tid < G1;
    const int p = isL1 ? tid : tid - G1;
    const int u = p >> 2;
    const int q = p & 3;

    // activation: s = sigmoid(scale*raw); act = actA*s + actB
    // q==2 (g gate) -> tanh via 2*sigmoid(2x)-1; others -> sigmoid
    const float scale = (q == 2) ? 2.0f : 1.0f;
    const float actA  = (q == 2) ? 2.0f : 1.0f;
    const float actB  = (q == 2) ? -1.0f : 0.0f;

    // packed weights (pairs of consecutive input elements)
    unsigned long long w2[48];
    float bias;
    if (isL1) {
        const int g = q * H1 + u;
        const float2* whh = reinterpret_cast<const float2*>(W_hh1 + g * H1);
        #pragma unroll
        for (int k = 0; k < 32; ++k) { const float2 v = whh[k]; w2[k] = pk2(v.x, v.y); }
        const float2* wih = reinterpret_cast<const float2*>(W_ih1 + g * INPUT_DIM);
        { float2 v = wih[0]; w2[32] = pk2(v.x, v.y); v = wih[1]; w2[33] = pk2(v.x, v.y); }
        #pragma unroll
        for (int k = 34; k < 48; ++k) w2[k] = 0ull;
        bias = b_ih1[g] + b_hh1[g];
    } else {
        const int g = q * H2 + u;
        const float2* wih = reinterpret_cast<const float2*>(W_ih2 + g * H1);
        #pragma unroll
        for (int k = 0; k < 32; ++k) { const float2 v = wih[k]; w2[k] = pk2(v.x, v.y); }
        const float2* whh = reinterpret_cast<const float2*>(W_hh2 + g * H2);
        #pragma unroll
        for (int k = 0; k < 16; ++k) { const float2 v = whh[k]; w2[32 + k] = pk2(v.x, v.y); }
        bias = b_ih2[g] + b_hh2[g];
    }

    float c = 0.0f;  // cell state; only meaningful in q==0 lanes

    const float* xb  = x + (size_t)b * SEQ * INPUT_DIM;
    float* outb      = out + (size_t)b * SEQ * H2;

    // -------- prologue: h1(0) from x(0), h1(-1)=0; h2(-1)=0 --------
    if (isL1) {
        const float4 xv = *reinterpret_cast<const float4*>(xb);
        unsigned long long a0 = fma2(w2[32], pk2(xv.x, xv.y), pk2(bias, 0.0f));
        a0 = fma2(w2[33], pk2(xv.z, xv.w), a0);
        float lo, hi; upk2(a0, lo, hi);
        const float raw = lo + hi;
        const float e = __expf(-scale * raw);
        const float s = __fdividef(1.0f, 1.0f + e);
        const float act = __fmaf_rn(actA, s, actB);
        const float v1 = __shfl_xor_sync(0xffffffffu, act, 1);
        const float v2 = __shfl_xor_sync(0xffffffffu, act, 2);
        const float v3 = __shfl_xor_sync(0xffffffffu, v1, 2);
        // lane q==0: i=act, f=v1, g=v2, o=v3
        c = __fmaf_rn(v1, c, act * v2);
        const float h = v3 * tanh_f(c);
        if (q == 0) h1_sh[0][u] = h;
    } else {
        if (q == 0) h2_sh[0][u] = 0.0f;
    }
    __syncthreads();

    // -------- main loop: one barrier per step --------
    // step t: L1 computes h1(t+1) from h1(t), x(t+1);  L2 computes h2(t) from h1(t), h2(t-1)
    for (int t = 0; t < SEQ; ++t) {
        const int rb = t & 1;
        const int wb = rb ^ 1;
        if (isL1) {
            if (t + 1 < SEQ) {
                const float4 xv = *reinterpret_cast<const float4*>(xb + (size_t)(t + 1) * INPUT_DIM);
                const ulonglong2* hv = reinterpret_cast<const ulonglong2*>(h1_sh[rb]);
                unsigned long long a0 = pk2(bias, 0.0f);
                unsigned long long a1 = 0ull, a2 = 0ull, a3 = 0ull;
                #pragma unroll
                for (int kk = 0; kk < 8; ++kk) {
                    const ulonglong2 hA = hv[2 * kk];
                    const ulonglong2 hB = hv[2 * kk + 1];
                    a0 = fma2(w2[4 * kk + 0], hA.x, a0);
                    a1 = fma2(w2[4 * kk + 1], hA.y, a1);
                    a2 = fma2(w2[4 * kk + 2], hB.x, a2);
                    a3 = fma2(w2[4 * kk + 3], hB.y, a3);
                }
                a0 = fma2(w2[32], pk2(xv.x, xv.y), a0);
                a1 = fma2(w2[33], pk2(xv.z, xv.w), a1);
                a0 = add2(a0, a1);
                a2 = add2(a2, a3);
                a0 = add2(a0, a2);
                float lo, hi; upk2(a0, lo, hi);
                const float raw = lo + hi;
                const float e = __expf(-scale * raw);
                const float s = __fdividef(1.0f, 1.0f + e);
                const float act = __fmaf_rn(actA, s, actB);
                const float v1 = __shfl_xor_sync(0xffffffffu, act, 1);
                const float v2 = __shfl_xor_sync(0xffffffffu, act, 2);
                const float v3 = __shfl_xor_sync(0xffffffffu, v1, 2);
                c = __fmaf_rn(v1, c, act * v2);
                const float h = v3 * tanh_f(c);
                if (q == 0) h1_sh[wb][u] = h;
            }
        } else {
            const ulonglong2* hv  = reinterpret_cast<const ulonglong2*>(h1_sh[rb]);
            const ulonglong2* h2v = reinterpret_cast<const ulonglong2*>(h2_sh[rb]);
            unsigned long long a0 = pk2(bias, 0.0f);
            unsigned long long a1 = 0ull, a2 = 0ull, a3 = 0ull;
            #pragma unroll
            for (int kk = 0; kk < 8; ++kk) {
                const ulonglong2 hA = hv[2 * kk];
                const ulonglong2 hB = hv[2 * kk + 1];
                a0 = fma2(w2[4 * kk + 0], hA.x, a0);
                a1 = fma2(w2[4 * kk + 1], hA.y, a1);
                a2 = fma2(w2[4 * kk + 2], hB.x, a2);
                a3 = fma2(w2[4 * kk + 3], hB.y, a3);
            }
            #pragma unroll
            for (int kk = 0; kk < 4; ++kk) {
                const ulonglong2 hA = h2v[2 * kk];
                const ulonglong2 hB = h2v[2 * kk + 1];
                a0 = fma2(w2[32 + 4 * kk + 0], hA.x, a0);
                a1 = fma2(w2[32 + 4 * kk + 1], hA.y, a1);
                a2 = fma2(w2[32 + 4 * kk + 2], hB.x, a2);
                a3 = fma2(w2[32 + 4 * kk + 3], hB.y, a3);
            }
            a0 = add2(a0, a1);
            a2 = add2(a2, a3);
            a0 = add2(a0, a2);
            float lo, hi; upk2(a0, lo, hi);
            const float raw = lo + hi;
            const float e = __expf(-scale * raw);
            const float s = __fdividef(1.0f, 1.0f + e);
            const float act = __fmaf_rn(actA, s, actB);
            const float v1 = __shfl_xor_sync(0xffffffffu, act, 1);
            const float v2 = __shfl_xor_sync(0xffffffffu, act, 2);
            const float v3 = __shfl_xor_sync(0xffffffffu, v1, 2);
            c = __fmaf_rn(v1, c, act * v2);
            const float h = v3 * tanh_f(c);
            if (q == 0) {
                h2_sh[wb][u] = h;
                outb[(size_t)t * H2 + u] = h;
            }
        }
        __syncthreads();
    }
}

extern "C" void kernel_launch(void* const* d_in, const int* in_sizes, int n_in,
                              void* d_out, int out_size) {
    const float* x     = (const float*)d_in[0];
    const float* W_ih1 = (const float*)d_in[1];
    const float* W_hh1 = (const float*)d_in[2];
    const float* b_ih1 = (const float*)d_in[3];
    const float* b_hh1 = (const float*)d_in[4];
    const float* W_ih2 = (const float*)d_in[5];
    const float* W_hh2 = (const float*)d_in[6];
    const float* b_ih2 = (const float*)d_in[7];
    const float* b_hh2 = (const float*)d_in[8];
    float* out = (float*)d_out;

    lstm2_kernel<<<BATCH, NTHREADS>>>(x, W_ih1, W_hh1, b_ih1, b_hh1,
                                      W_ih2, W_hh2, b_ih2, b_hh2, out);
}

// round 3
// speedup vs baseline: 1.1441x; 1.1441x over previous
#include <cuda_runtime.h>
#include <cuda_bf16.h>

// Problem constants
#define INPUT_DIM 4
#define H1 64          // hidden_dim
#define H2 32          // latent_dim
#define BATCH 64
#define SEQ 4096

#define G1 (4*H1)      // 256 layer-1 gate lanes
#define G2 (4*H2)      // 128 layer-2 gate lanes
#define NTHREADS (G1 + G2)  // 384

__device__ __forceinline__ float tanh_approx(float x) {
    float y;
    asm("tanh.approx.f32 %0, %1;" : "=f"(y) : "f"(x));
    return y;
}

__global__ void __launch_bounds__(NTHREADS, 1)
lstm2_kernel(const float* __restrict__ x,
             const float* __restrict__ W_ih1, const float* __restrict__ W_hh1,
             const float* __restrict__ b_ih1, const float* __restrict__ b_hh1,
             const float* __restrict__ W_ih2, const float* __restrict__ W_hh2,
             const float* __restrict__ b_ih2, const float* __restrict__ b_hh2,
             float* __restrict__ out)
{
    const int b   = blockIdx.x;
    const int tid = threadIdx.x;

    // double-buffered hidden states; one __syncthreads per step
    __shared__ __align__(16) float h1_sh[2][H1];
    __shared__ __align__(16) float h2_sh[2][H2];

    // Lane layout: 4 lanes per hidden unit, one gate per lane.
    // tid < 256 : layer-1, unit u = p>>2, gate q = p&3 (i,f,g,o)
    // tid >= 256: layer-2, same pattern
    const bool isL1 = tid < G1;
    const int p = isL1 ? tid : tid - G1;
    const int u = p >> 2;
    const int q = p & 3;

    // unified activation: act = A * tanh(s*x) + B
    //   q==2 (g): tanh      -> s=1,   A=1,   B=0
    //   else (sigmoid)      -> s=0.5, A=0.5, B=0.5
    const float actS = (q == 2) ? 1.0f : 0.5f;
    const float actA = (q == 2) ? 1.0f : 0.5f;
    const float actB = (q == 2) ? 0.0f : 0.5f;

    // register weights
    float w[96];
    float bias;
    if (isL1) {
        const int g = q * H1 + u;
        #pragma unroll
        for (int k = 0; k < 64; ++k) w[k] = W_hh1[g * 64 + k];
        #pragma unroll
        for (int k = 0; k < 4; ++k)  w[64 + k] = W_ih1[g * 4 + k];
        #pragma unroll
        for (int k = 68; k < 96; ++k) w[k] = 0.0f;
        bias = b_ih1[g] + b_hh1[g];
    } else {
        const int g = q * H2 + u;
        #pragma unroll
        for (int k = 0; k < 64; ++k) w[k] = W_ih2[g * 64 + k];   // vs h1
        #pragma unroll
        for (int k = 0; k < 32; ++k) w[64 + k] = W_hh2[g * 32 + k]; // vs h2
        bias = b_ih2[g] + b_hh2[g];
    }

    float c = 0.0f;  // valid only in q==0 lanes

    const float* xb = x + (size_t)b * SEQ * INPUT_DIM;
    float* outb     = out + (size_t)b * SEQ * H2;

    // -------- prologue: h1(0) from x(0) with h1(-1)=0; h2(-1)=0 --------
    if (isL1) {
        const float4 xv = *reinterpret_cast<const float4*>(xb);
        const float raw = bias + w[64]*xv.x + w[65]*xv.y + w[66]*xv.z + w[67]*xv.w;
        const float act = __fmaf_rn(actA, tanh_approx(actS * raw), actB);
        const float v1 = __shfl_xor_sync(0xffffffffu, act, 1);
        const float v2 = __shfl_xor_sync(0xffffffffu, act, 2);
        const float v3 = __shfl_xor_sync(0xffffffffu, act, 3);
        c = __fmaf_rn(v1, c, act * v2);
        const float h = v3 * tanh_approx(c);
        if (q == 0) h1_sh[0][u] = h;
    } else {
        if (q == 0) h2_sh[0][u] = 0.0f;
    }
    __syncthreads();

    // -------- main loop: one barrier per step --------
    // step t: L1 computes h1(t+1) from h1(t),x(t+1); L2 computes h2(t) from h1(t),h2(t-1)
    for (int t = 0; t < SEQ; ++t) {
        const int rb = t & 1;
        const int wb = rb ^ 1;
        if (isL1) {
            if (t + 1 < SEQ) {
                // prefetch x early (independent of LDS)
                const float4 xv = *reinterpret_cast<const float4*>(xb + (size_t)(t + 1) * INPUT_DIM);
                const float4* hv = reinterpret_cast<const float4*>(h1_sh[rb]);
                float a0 = bias, a1 = 0.f, a2 = 0.f, a3 = 0.f,
                      a4 = 0.f,  a5 = 0.f, a6 = 0.f, a7 = 0.f;
                #pragma unroll
                for (int kk = 0; kk < 8; ++kk) {
                    const float4 A = hv[2 * kk];
                    const float4 B = hv[2 * kk + 1];
                    a0 = __fmaf_rn(w[8*kk+0], A.x, a0);
                    a1 = __fmaf_rn(w[8*kk+1], A.y, a1);
                    a2 = __fmaf_rn(w[8*kk+2], A.z, a2);
                    a3 = __fmaf_rn(w[8*kk+3], A.w, a3);
                    a4 = __fmaf_rn(w[8*kk+4], B.x, a4);
                    a5 = __fmaf_rn(w[8*kk+5], B.y, a5);
                    a6 = __fmaf_rn(w[8*kk+6], B.z, a6);
                    a7 = __fmaf_rn(w[8*kk+7], B.w, a7);
                }
                a0 = __fmaf_rn(w[64], xv.x, a0);
                a1 = __fmaf_rn(w[65], xv.y, a1);
                a2 = __fmaf_rn(w[66], xv.z, a2);
                a3 = __fmaf_rn(w[67], xv.w, a3);
                const float raw = ((a0 + a1) + (a2 + a3)) + ((a4 + a5) + (a6 + a7));
                const float act = __fmaf_rn(actA, tanh_approx(actS * raw), actB);
                const float v1 = __shfl_xor_sync(0xffffffffu, act, 1);
                const float v2 = __shfl_xor_sync(0xffffffffu, act, 2);
                const float v3 = __shfl_xor_sync(0xffffffffu, act, 3);
                c = __fmaf_rn(v1, c, act * v2);
                const float h = v3 * tanh_approx(c);
                if (q == 0) h1_sh[wb][u] = h;
            }
        } else {
            const float4* hv  = reinterpret_cast<const float4*>(h1_sh[rb]);
            const float4* h2v = reinterpret_cast<const float4*>(h2_sh[rb]);
            float a0 = bias, a1 = 0.f, a2 = 0.f, a3 = 0.f,
                  a4 = 0.f,  a5 = 0.f, a6 = 0.f, a7 = 0.f;
            #pragma unroll
            for (int kk = 0; kk < 8; ++kk) {
                const float4 A = hv[2 * kk];
                const float4 B = hv[2 * kk + 1];
                a0 = __fmaf_rn(w[8*kk+0], A.x, a0);
                a1 = __fmaf_rn(w[8*kk+1], A.y, a1);
                a2 = __fmaf_rn(w[8*kk+2], A.z, a2);
                a3 = __fmaf_rn(w[8*kk+3], A.w, a3);
                a4 = __fmaf_rn(w[8*kk+4], B.x, a4);
                a5 = __fmaf_rn(w[8*kk+5], B.y, a5);
                a6 = __fmaf_rn(w[8*kk+6], B.z, a6);
                a7 = __fmaf_rn(w[8*kk+7], B.w, a7);
            }
            #pragma unroll
            for (int kk = 0; kk < 4; ++kk) {
                const float4 A = h2v[2 * kk];
                const float4 B = h2v[2 * kk + 1];
                a0 = __fmaf_rn(w[64+8*kk+0], A.x, a0);
                a1 = __fmaf_rn(w[64+8*kk+1], A.y, a1);
                a2 = __fmaf_rn(w[64+8*kk+2], A.z, a2);
                a3 = __fmaf_rn(w[64+8*kk+3], A.w, a3);
                a4 = __fmaf_rn(w[64+8*kk+4], B.x, a4);
                a5 = __fmaf_rn(w[64+8*kk+5], B.y, a5);
                a6 = __fmaf_rn(w[64+8*kk+6], B.z, a6);
                a7 = __fmaf_rn(w[64+8*kk+7], B.w, a7);
            }
            const float raw = ((a0 + a1) + (a2 + a3)) + ((a4 + a5) + (a6 + a7));
            const float act = __fmaf_rn(actA, tanh_approx(actS * raw), actB);
            const float v1 = __shfl_xor_sync(0xffffffffu, act, 1);
            const float v2 = __shfl_xor_sync(0xffffffffu, act, 2);
            const float v3 = __shfl_xor_sync(0xffffffffu, act, 3);
            c = __fmaf_rn(v1, c, act * v2);
            const float h = v3 * tanh_approx(c);
            if (q == 0) {
                h2_sh[wb][u] = h;
                outb[(size_t)t * H2 + u] = h;
            }
        }
        __syncthreads();
    }
}

extern "C" void kernel_launch(void* const* d_in, const int* in_sizes, int n_in,
                              void* d_out, int out_size) {
    const float* x     = (const float*)d_in[0];
    const float* W_ih1 = (const float*)d_in[1];
    const float* W_hh1 = (const float*)d_in[2];
    const float* b_ih1 = (const float*)d_in[3];
    const float* b_hh1 = (const float*)d_in[4];
    const float* W_ih2 = (const float*)d_in[5];
    const float* W_hh2 = (const float*)d_in[6];
    const float* b_ih2 = (const float*)d_in[7];
    const float* b_hh2 = (const float*)d_in[8];
    float* out = (float*)d_out;

    lstm2_kernel<<<BATCH, NTHREADS>>>(x, W_ih1, W_hh1, b_ih1, b_hh1,
                                      W_ih2, W_hh2, b_ih2, b_hh2, out);
}

// round 4
// speedup vs baseline: 1.1836x; 1.0345x over previous
#include <cuda_runtime.h>
#include <cuda_bf16.h>

#define INPUT_DIM 4
#define H1 64
#define H2 32
#define BATCH 64
#define SEQ 4096

#define G1 (4*H1)           // 256 layer-1 lanes
#define G2 (4*H2)           // 128 layer-2 lanes
#define NTHREADS (G1 + G2)  // 384
#define RING 8              // h1 ring depth (power of 2)

// ---- packed f32x2 helpers ----
__device__ __forceinline__ unsigned long long pk2(float a, float b) {
    unsigned long long r;
    asm("mov.b64 %0, {%1, %2};" : "=l"(r) : "f"(a), "f"(b));
    return r;
}
__device__ __forceinline__ void upk2(unsigned long long v, float& a, float& b) {
    asm("mov.b64 {%0, %1}, %2;" : "=f"(a), "=f"(b) : "l"(v));
}
__device__ __forceinline__ unsigned long long fma2(unsigned long long a,
                                                   unsigned long long b,
                                                   unsigned long long c) {
    unsigned long long d;
    asm("fma.rn.f32x2 %0, %1, %2, %3;" : "=l"(d) : "l"(a), "l"(b), "l"(c));
    return d;
}
__device__ __forceinline__ unsigned long long add2(unsigned long long a,
                                                   unsigned long long b) {
    unsigned long long d;
    asm("add.rn.f32x2 %0, %1, %2;" : "=l"(d) : "l"(a), "l"(b));
    return d;
}

__device__ __forceinline__ float tanh_approx(float x) {
    float y;
    asm("tanh.approx.f32 %0, %1;" : "=f"(y) : "f"(x));
    return y;
}

// acquire/release flag ops (cta scope, generic addr -> shared)
__device__ __forceinline__ int ld_acq(const int* p) {
    int v;
    asm volatile("ld.acquire.cta.b32 %0, [%1];" : "=r"(v) : "l"(p) : "memory");
    return v;
}
__device__ __forceinline__ void st_rel(int* p, int v) {
    asm volatile("st.release.cta.b32 [%0], %1;" :: "l"(p), "r"(v) : "memory");
}

__device__ __forceinline__ void bar_sync(int id, int cnt) {
    asm volatile("bar.sync %0, %1;" :: "r"(id), "r"(cnt) : "memory");
}

__global__ void __launch_bounds__(NTHREADS, 1)
lstm2_kernel(const float* __restrict__ x,
             const float* __restrict__ W_ih1, const float* __restrict__ W_hh1,
             const float* __restrict__ b_ih1, const float* __restrict__ b_hh1,
             const float* __restrict__ W_ih2, const float* __restrict__ W_hh2,
             const float* __restrict__ b_ih2, const float* __restrict__ b_hh2,
             float* __restrict__ out)
{
    const int b   = blockIdx.x;
    const int tid = threadIdx.x;

    __shared__ __align__(16) float h1ring[RING][H1];
    __shared__ __align__(16) float h2buf[2][H2];
    __shared__ int l1_done;   // last step L1 has published
    __shared__ int l2_done;   // last step L2 has fully consumed

    const bool isL1 = tid < G1;
    const int p = isL1 ? tid : tid - G1;
    const int u = p >> 2;      // hidden unit
    const int q = p & 3;       // gate (i,f,g,o)

    // unified activation: act = A*tanh(S*x)+B ; g-gate: tanh, others: sigmoid
    const float actS = (q == 2) ? 1.0f : 0.5f;
    const float actA = (q == 2) ? 1.0f : 0.5f;
    const float actB = (q == 2) ? 0.0f : 0.5f;

    // -------- shared init --------
    if (tid == 0) { l1_done = -1; l2_done = -1; }
    if (isL1 && q == 0) h1ring[RING - 1][u] = 0.0f;   // h1(-1) = 0 lives in slot RING-1
    if (!isL1 && q == 0) h2buf[0][u] = 0.0f;          // h2(-1) = 0 lives in buf 0
    __syncthreads();

    if (isL1) {
        // ================= Layer-1 producer =================
        const int g = q * H1 + u;
        unsigned long long w2[34];
        {
            const float2* whh = reinterpret_cast<const float2*>(W_hh1 + g * H1);
            #pragma unroll
            for (int k = 0; k < 32; ++k) { const float2 v = whh[k]; w2[k] = pk2(v.x, v.y); }
            const float2* wih = reinterpret_cast<const float2*>(W_ih1 + g * INPUT_DIM);
            { float2 v = wih[0]; w2[32] = pk2(v.x, v.y); v = wih[1]; w2[33] = pk2(v.x, v.y); }
        }
        const float bias = b_ih1[g] + b_hh1[g];
        const float4* xb4 = reinterpret_cast<const float4*>(x + (size_t)b * SEQ * INPUT_DIM);

        float c = 0.0f;
        int consumed = -1;
        float4 xv = __ldg(xb4);          // x(0)

        #pragma unroll 1
        for (int t = 0; t < SEQ; ++t) {
            // prefetch x(t+1) early
            const int tn = (t + 1 < SEQ) ? (t + 1) : t;
            const float4 xv_next = __ldg(xb4 + tn);

            // backpressure: writing slot t&7 overwrites h1(t-8); L2 must be done with it
            if (consumed < t - RING) {
                do { consumed = ld_acq(&l2_done); } while (consumed < t - RING);
            }

            // gates(t) = W_hh1 * h1(t-1) + W_ih1 * x(t) + bias
            const ulonglong2* hv = reinterpret_cast<const ulonglong2*>(h1ring[(t + RING - 1) & (RING - 1)]);
            unsigned long long a0 = pk2(bias, 0.0f);
            unsigned long long a1 = fma2(w2[32], pk2(xv.x, xv.y), 0ull);
            unsigned long long a2 = fma2(w2[33], pk2(xv.z, xv.w), 0ull);
            unsigned long long a3 = 0ull;
            #pragma unroll
            for (int kk = 0; kk < 8; ++kk) {
                const ulonglong2 hA = hv[2 * kk];
                const ulonglong2 hB = hv[2 * kk + 1];
                a0 = fma2(w2[4 * kk + 0], hA.x, a0);
                a1 = fma2(w2[4 * kk + 1], hA.y, a1);
                a2 = fma2(w2[4 * kk + 2], hB.x, a2);
                a3 = fma2(w2[4 * kk + 3], hB.y, a3);
            }
            a0 = add2(a0, a1);
            a2 = add2(a2, a3);
            a0 = add2(a0, a2);
            float lo, hi; upk2(a0, lo, hi);
            const float raw = lo + hi;

            const float act = __fmaf_rn(actA, tanh_approx(actS * raw), actB);
            const float v1 = __shfl_xor_sync(0xffffffffu, act, 1);
            const float v2 = __shfl_xor_sync(0xffffffffu, act, 2);
            const float v3 = __shfl_xor_sync(0xffffffffu, act, 3);
            c = __fmaf_rn(v1, c, act * v2);
            const float h = v3 * tanh_approx(c);

            if (q == 0) h1ring[t & (RING - 1)][u] = h;
            bar_sync(1, G1);                       // L1-internal: h1(t) visible to all L1
            if (tid == 0) st_rel(&l1_done, t);     // publish to L2
            xv = xv_next;
        }
    } else {
        // ================= Layer-2 consumer =================
        const int g = q * H2 + u;
        unsigned long long w2[48];
        {
            const float2* wih = reinterpret_cast<const float2*>(W_ih2 + g * H1);
            #pragma unroll
            for (int k = 0; k < 32; ++k) { const float2 v = wih[k]; w2[k] = pk2(v.x, v.y); }
            const float2* whh = reinterpret_cast<const float2*>(W_hh2 + g * H2);
            #pragma unroll
            for (int k = 0; k < 16; ++k) { const float2 v = whh[k]; w2[32 + k] = pk2(v.x, v.y); }
        }
        const float bias = b_ih2[g] + b_hh2[g];
        float* outb = out + (size_t)b * SEQ * H2;

        float c = 0.0f;
        int avail = -1;

        #pragma unroll 1
        for (int t = 0; t < SEQ; ++t) {
            // wait for h1(t)
            if (avail < t) {
                do { avail = ld_acq(&l1_done); } while (avail < t);
            }

            const ulonglong2* hv = reinterpret_cast<const ulonglong2*>(h1ring[t & (RING - 1)]);
            const ulonglong2* gv = reinterpret_cast<const ulonglong2*>(h2buf[t & 1]);

            unsigned long long a0 = pk2(bias, 0.0f);
            unsigned long long a1 = 0ull, a2 = 0ull, a3 = 0ull;
            #pragma unroll
            for (int kk = 0; kk < 8; ++kk) {
                const ulonglong2 hA = hv[2 * kk];
                const ulonglong2 hB = hv[2 * kk + 1];
                a0 = fma2(w2[4 * kk + 0], hA.x, a0);
                a1 = fma2(w2[4 * kk + 1], hA.y, a1);
                a2 = fma2(w2[4 * kk + 2], hB.x, a2);
                a3 = fma2(w2[4 * kk + 3], hB.y, a3);
            }
            #pragma unroll
            for (int kk = 0; kk < 4; ++kk) {
                const ulonglong2 hA = gv[2 * kk];
                const ulonglong2 hB = gv[2 * kk + 1];
                a0 = fma2(w2[32 + 4 * kk + 0], hA.x, a0);
                a1 = fma2(w2[32 + 4 * kk + 1], hA.y, a1);
                a2 = fma2(w2[32 + 4 * kk + 2], hB.x, a2);
                a3 = fma2(w2[32 + 4 * kk + 3], hB.y, a3);
            }
            a0 = add2(a0, a1);
            a2 = add2(a2, a3);
            a0 = add2(a0, a2);
            float lo, hi; upk2(a0, lo, hi);
            const float raw = lo + hi;

            const float act = __fmaf_rn(actA, tanh_approx(actS * raw), actB);
            const float v1 = __shfl_xor_sync(0xffffffffu, act, 1);
            const float v2 = __shfl_xor_sync(0xffffffffu, act, 2);
            const float v3 = __shfl_xor_sync(0xffffffffu, act, 3);
            c = __fmaf_rn(v1, c, act * v2);
            const float h = v3 * tanh_approx(c);

            if (q == 0) {
                h2buf[(t + 1) & 1][u] = h;
                outb[(size_t)t * H2 + u] = h;
            }
            bar_sync(2, G2);                        // L2-internal
            if (tid == G1) st_rel(&l2_done, t);     // release ring slot t
        }
    }
}

extern "C" void kernel_launch(void* const* d_in, const int* in_sizes, int n_in,
                              void* d_out, int out_size) {
    const float* x     = (const float*)d_in[0];
    const float* W_ih1 = (const float*)d_in[1];
    const float* W_hh1 = (const float*)d_in[2];
    const float* b_ih1 = (const float*)d_in[3];
    const float* b_hh1 = (const float*)d_in[4];
    const float* W_ih2 = (const float*)d_in[5];
    const float* W_hh2 = (const float*)d_in[6];
    const float* b_ih2 = (const float*)d_in[7];
    const float* b_hh2 = (const float*)d_in[8];
    float* out = (float*)d_out;

    lstm2_kernel<<<BATCH, NTHREADS>>>(x, W_ih1, W_hh1, b_ih1, b_hh1,
                                      W_ih2, W_hh2, b_ih2, b_hh2, out);
}

// round 5
// speedup vs baseline: 1.3488x; 1.1396x over previous
#include <cuda_runtime.h>
#include <cuda_bf16.h>

#define INPUT_DIM 4
#define H1 64
#define H2 32
#define BATCH 64
#define SEQ 4096

#define NT_L1 128           // layer-1: 2 gates per thread
#define NT_L2 128           // layer-2: 1 gate per thread (R4 layout)
#define NTHREADS (NT_L1 + NT_L2)
#define RING 8

// ---- packed f32x2 helpers ----
__device__ __forceinline__ unsigned long long pk2(float a, float b) {
    unsigned long long r;
    asm("mov.b64 %0, {%1, %2};" : "=l"(r) : "f"(a), "f"(b));
    return r;
}
__device__ __forceinline__ void upk2(unsigned long long v, float& a, float& b) {
    asm("mov.b64 {%0, %1}, %2;" : "=f"(a), "=f"(b) : "l"(v));
}
__device__ __forceinline__ unsigned long long fma2(unsigned long long a,
                                                   unsigned long long b,
                                                   unsigned long long c) {
    unsigned long long d;
    asm("fma.rn.f32x2 %0, %1, %2, %3;" : "=l"(d) : "l"(a), "l"(b), "l"(c));
    return d;
}
__device__ __forceinline__ unsigned long long add2(unsigned long long a,
                                                   unsigned long long b) {
    unsigned long long d;
    asm("add.rn.f32x2 %0, %1, %2;" : "=l"(d) : "l"(a), "l"(b));
    return d;
}
__device__ __forceinline__ float tanh_approx(float x) {
    float y;
    asm("tanh.approx.f32 %0, %1;" : "=f"(y) : "f"(x));
    return y;
}
__device__ __forceinline__ int ld_acq(const int* p) {
    int v;
    asm volatile("ld.acquire.cta.b32 %0, [%1];" : "=r"(v) : "l"(p) : "memory");
    return v;
}
__device__ __forceinline__ void st_rel(int* p, int v) {
    asm volatile("st.release.cta.b32 [%0], %1;" :: "l"(p), "r"(v) : "memory");
}
__device__ __forceinline__ void bar_sync(int id, int cnt) {
    asm volatile("bar.sync %0, %1;" :: "r"(id), "r"(cnt) : "memory");
}

__global__ void __launch_bounds__(NTHREADS, 1)
lstm2_kernel(const float* __restrict__ x,
             const float* __restrict__ W_ih1, const float* __restrict__ W_hh1,
             const float* __restrict__ b_ih1, const float* __restrict__ b_hh1,
             const float* __restrict__ W_ih2, const float* __restrict__ W_hh2,
             const float* __restrict__ b_ih2, const float* __restrict__ b_hh2,
             float* __restrict__ out)
{
    const int b   = blockIdx.x;
    const int tid = threadIdx.x;

    __shared__ __align__(16) float h1ring[RING][H1];
    __shared__ __align__(16) float h2buf[2][H2];
    __shared__ int l1_done;
    __shared__ int l2_done;

    const bool isL1 = tid < NT_L1;

    if (tid == 0) { l1_done = -1; l2_done = -1; }
    // h1(-1) = 0 lives in slot RING-1; written by odd L1 lanes (u = tid>>1)
    if (isL1 && (tid & 1)) h1ring[RING - 1][tid >> 1] = 0.0f;
    // h2(-1) = 0 in buf 0; written by L2 q==0 lanes
    if (!isL1 && (((tid - NT_L1) & 3) == 0)) h2buf[0][(tid - NT_L1) >> 2] = 0.0f;
    __syncthreads();

    if (isL1) {
        // ======== Layer 1: 2 gates per thread ========
        // unit u = tid>>1, parity par = tid&1
        //   par==0: gateA = i (row u),        gateB = g (row 2*H1+u)
        //   par==1: gateA = f (row H1+u),     gateB = o (row 3*H1+u)
        const int u   = tid >> 1;
        const int par = tid & 1;
        const int rowA = par * H1 + u;
        const int rowB = (2 + par) * H1 + u;

        // gateA is always sigmoid; gateB: par0 -> tanh, par1 -> sigmoid
        const float bS = par ? 0.5f : 1.0f;
        const float bA = par ? 0.5f : 1.0f;
        const float bB = par ? 0.5f : 0.0f;

        unsigned long long wA[32], wB[32], xA0, xA1, xB0, xB1;
        {
            const float2* whhA = reinterpret_cast<const float2*>(W_hh1 + rowA * H1);
            const float2* whhB = reinterpret_cast<const float2*>(W_hh1 + rowB * H1);
            #pragma unroll
            for (int k = 0; k < 32; ++k) {
                float2 v = whhA[k]; wA[k] = pk2(v.x, v.y);
                float2 w = whhB[k]; wB[k] = pk2(w.x, w.y);
            }
            const float2* wihA = reinterpret_cast<const float2*>(W_ih1 + rowA * INPUT_DIM);
            const float2* wihB = reinterpret_cast<const float2*>(W_ih1 + rowB * INPUT_DIM);
            float2 v;
            v = wihA[0]; xA0 = pk2(v.x, v.y);
            v = wihA[1]; xA1 = pk2(v.x, v.y);
            v = wihB[0]; xB0 = pk2(v.x, v.y);
            v = wihB[1]; xB1 = pk2(v.x, v.y);
        }
        const float biasA = b_ih1[rowA] + b_hh1[rowA];
        const float biasB = b_ih1[rowB] + b_hh1[rowB];

        const float4* xb4 = reinterpret_cast<const float4*>(x + (size_t)b * SEQ * INPUT_DIM);
        float c = 0.0f;          // valid in par==1 lanes
        int consumed = -1;
        float4 xv = __ldg(xb4);  // x(0)

        #pragma unroll 1
        for (int t = 0; t < SEQ; ++t) {
            const int tn = (t + 1 < SEQ) ? (t + 1) : t;
            const float4 xv_next = __ldg(xb4 + tn);

            if (consumed < t - RING) {
                do { consumed = ld_acq(&l2_done); } while (consumed < t - RING);
            }

            const ulonglong2* hv =
                reinterpret_cast<const ulonglong2*>(h1ring[(t + RING - 1) & (RING - 1)]);
            const unsigned long long xp0 = pk2(xv.x, xv.y);
            const unsigned long long xp1 = pk2(xv.z, xv.w);

            unsigned long long a0 = pk2(biasA, 0.0f), a1 = 0ull, a2 = 0ull, a3 = 0ull;
            unsigned long long d0 = pk2(biasB, 0.0f), d1 = 0ull, d2 = 0ull, d3 = 0ull;
            #pragma unroll
            for (int kk = 0; kk < 8; ++kk) {
                const ulonglong2 hA = hv[2 * kk];
                const ulonglong2 hB = hv[2 * kk + 1];
                a0 = fma2(wA[4 * kk + 0], hA.x, a0);
                d0 = fma2(wB[4 * kk + 0], hA.x, d0);
                a1 = fma2(wA[4 * kk + 1], hA.y, a1);
                d1 = fma2(wB[4 * kk + 1], hA.y, d1);
                a2 = fma2(wA[4 * kk + 2], hB.x, a2);
                d2 = fma2(wB[4 * kk + 2], hB.x, d2);
                a3 = fma2(wA[4 * kk + 3], hB.y, a3);
                d3 = fma2(wB[4 * kk + 3], hB.y, d3);
            }
            a0 = fma2(xA0, xp0, a0); a1 = fma2(xA1, xp1, a1);
            d0 = fma2(xB0, xp0, d0); d1 = fma2(xB1, xp1, d1);
            a0 = add2(add2(a0, a1), add2(a2, a3));
            d0 = add2(add2(d0, d1), add2(d2, d3));
            float alo, ahi, dlo, dhi;
            upk2(a0, alo, ahi); upk2(d0, dlo, dhi);
            const float rawA = alo + ahi;
            const float rawB = dlo + dhi;

            // sA = sigmoid(rawA); sB = par0 ? tanh(rawB) : sigmoid(rawB)
            const float sA = __fmaf_rn(0.5f, tanh_approx(0.5f * rawA), 0.5f);
            const float sB = __fmaf_rn(bA, tanh_approx(bS * rawB), bB);

            // par0: val = i*g  -> sent to par1.  par1: val unused by partner.
            const float val = sA * sB;
            const float ig  = __shfl_xor_sync(0xffffffffu, val, 1);
            // par1: c = f*c + i*g ; h = o * tanh(c)
            c = __fmaf_rn(sA, c, ig);
            const float h = sB * tanh_approx(c);
            if (par) h1ring[t & (RING - 1)][u] = h;

            bar_sync(1, NT_L1);
            if (tid == 0) st_rel(&l1_done, t);
            xv = xv_next;
        }
    } else {
        // ======== Layer 2: 1 gate per thread (R4 layout) ========
        const int p = tid - NT_L1;
        const int u = p >> 2;
        const int q = p & 3;
        const float actS = (q == 2) ? 1.0f : 0.5f;
        const float actA = (q == 2) ? 1.0f : 0.5f;
        const float actB = (q == 2) ? 0.0f : 0.5f;

        const int g = q * H2 + u;
        unsigned long long w2[48];
        {
            const float2* wih = reinterpret_cast<const float2*>(W_ih2 + g * H1);
            #pragma unroll
            for (int k = 0; k < 32; ++k) { const float2 v = wih[k]; w2[k] = pk2(v.x, v.y); }
            const float2* whh = reinterpret_cast<const float2*>(W_hh2 + g * H2);
            #pragma unroll
            for (int k = 0; k < 16; ++k) { const float2 v = whh[k]; w2[32 + k] = pk2(v.x, v.y); }
        }
        const float bias = b_ih2[g] + b_hh2[g];
        float* outb = out + (size_t)b * SEQ * H2;

        float c = 0.0f;
        int avail = -1;

        #pragma unroll 1
        for (int t = 0; t < SEQ; ++t) {
            if (avail < t) {
                do { avail = ld_acq(&l1_done); } while (avail < t);
            }

            const ulonglong2* hv = reinterpret_cast<const ulonglong2*>(h1ring[t & (RING - 1)]);
            const ulonglong2* gv = reinterpret_cast<const ulonglong2*>(h2buf[t & 1]);

            unsigned long long a0 = pk2(bias, 0.0f);
            unsigned long long a1 = 0ull, a2 = 0ull, a3 = 0ull;
            #pragma unroll
            for (int kk = 0; kk < 8; ++kk) {
                const ulonglong2 hA = hv[2 * kk];
                const ulonglong2 hB = hv[2 * kk + 1];
                a0 = fma2(w2[4 * kk + 0], hA.x, a0);
                a1 = fma2(w2[4 * kk + 1], hA.y, a1);
                a2 = fma2(w2[4 * kk + 2], hB.x, a2);
                a3 = fma2(w2[4 * kk + 3], hB.y, a3);
            }
            #pragma unroll
            for (int kk = 0; kk < 4; ++kk) {
                const ulonglong2 hA = gv[2 * kk];
                const ulonglong2 hB = gv[2 * kk + 1];
                a0 = fma2(w2[32 + 4 * kk + 0], hA.x, a0);
                a1 = fma2(w2[32 + 4 * kk + 1], hA.y, a1);
                a2 = fma2(w2[32 + 4 * kk + 2], hB.x, a2);
                a3 = fma2(w2[32 + 4 * kk + 3], hB.y, a3);
            }
            a0 = add2(add2(a0, a1), add2(a2, a3));
            float lo, hi; upk2(a0, lo, hi);
            const float raw = lo + hi;

            const float act = __fmaf_rn(actA, tanh_approx(actS * raw), actB);
            const float v1 = __shfl_xor_sync(0xffffffffu, act, 1);
            const float v2 = __shfl_xor_sync(0xffffffffu, act, 2);
            const float v3 = __shfl_xor_sync(0xffffffffu, act, 3);
            c = __fmaf_rn(v1, c, act * v2);
            const float h = v3 * tanh_approx(c);

            if (q == 0) {
                h2buf[(t + 1) & 1][u] = h;
                outb[(size_t)t * H2 + u] = h;
            }
            bar_sync(2, NT_L2);
            if (tid == NT_L1) st_rel(&l2_done, t);
        }
    }
}

extern "C" void kernel_launch(void* const* d_in, const int* in_sizes, int n_in,
                              void* d_out, int out_size) {
    const float* x     = (const float*)d_in[0];
    const float* W_ih1 = (const float*)d_in[1];
    const float* W_hh1 = (const float*)d_in[2];
    const float* b_ih1 = (const float*)d_in[3];
    const float* b_hh1 = (const float*)d_in[4];
    const float* W_ih2 = (const float*)d_in[5];
    const float* W_hh2 = (const float*)d_in[6];
    const float* b_ih2 = (const float*)d_in[7];
    const float* b_hh2 = (const float*)d_in[8];
    float* out = (float*)d_out;

    lstm2_kernel<<<BATCH, NTHREADS>>>(x, W_ih1, W_hh1, b_ih1, b_hh1,
                                      W_ih2, W_hh2, b_ih2, b_hh2, out);
}